// round 7
// baseline (speedup 1.0000x reference)
#include <cuda_runtime.h>
#include <math.h>

#define NEXP    8
#define HDIM    4096
#define WARPS   24
#define THREADS 768
#define BLOCKS  152
#define NTOK    16384                 // 4 * 4096 tokens
#define NWARP   (BLOCKS * WARPS)      // 3648
#define H4      (HDIM / 4)            // 1024 float4 per row
#define KITERS  (H4 / 32)             // 32 k-iterations
// exact token partition: first RBIG warps own 5 tokens, rest own 4
#define TOK_BIG   5
#define TOK_SMALL 4
#define RBIG      (NTOK - TOK_SMALL * NWARP)   // 1792

// One warp processes TOKN consecutive tokens, single-buffered, phased weights.
template<int TOKN>
__device__ __forceinline__ void process_group(size_t t0, int lane,
                                              const float4* __restrict__ hsb,
                                              const float4* __restrict__ sw4,
                                              float* __restrict__ out_w,
                                              float* __restrict__ out_i,
                                              float* __restrict__ out_l)
{
    const float4* hs4 = hsb + t0 * H4;

    float acc[TOKN][NEXP];
    #pragma unroll
    for (int t = 0; t < TOKN; t++)
        #pragma unroll
        for (int e = 0; e < NEXP; e++)
            acc[t][e] = 0.0f;

    #pragma unroll 1
    for (int i = 0; i < KITERS; i++) {
        const int kk = i * 32 + lane;

        // issue all independent hidden loads first
        float4 h[TOKN];
        #pragma unroll
        for (int t = 0; t < TOKN; t++)
            h[t] = __ldcs(&hs4[(size_t)t * H4 + kk]);

        // phase 0: experts 0..3
        {
            float4 w[4];
            #pragma unroll
            for (int e = 0; e < 4; e++)
                w[e] = sw4[e * H4 + kk];
            #pragma unroll
            for (int t = 0; t < TOKN; t++)
                #pragma unroll
                for (int e = 0; e < 4; e++) {
                    acc[t][e] = fmaf(h[t].x, w[e].x, acc[t][e]);
                    acc[t][e] = fmaf(h[t].y, w[e].y, acc[t][e]);
                    acc[t][e] = fmaf(h[t].z, w[e].z, acc[t][e]);
                    acc[t][e] = fmaf(h[t].w, w[e].w, acc[t][e]);
                }
        }
        // phase 1: experts 4..7
        {
            float4 w[4];
            #pragma unroll
            for (int e = 0; e < 4; e++)
                w[e] = sw4[(e + 4) * H4 + kk];
            #pragma unroll
            for (int t = 0; t < TOKN; t++)
                #pragma unroll
                for (int e = 0; e < 4; e++) {
                    acc[t][e + 4] = fmaf(h[t].x, w[e].x, acc[t][e + 4]);
                    acc[t][e + 4] = fmaf(h[t].y, w[e].y, acc[t][e + 4]);
                    acc[t][e + 4] = fmaf(h[t].z, w[e].z, acc[t][e + 4]);
                    acc[t][e + 4] = fmaf(h[t].w, w[e].w, acc[t][e + 4]);
                }
        }
    }

    // Butterfly reduction (once per warp per kernel — amortized)
    #pragma unroll
    for (int off = 16; off > 0; off >>= 1) {
        #pragma unroll
        for (int t = 0; t < TOKN; t++)
            #pragma unroll
            for (int e = 0; e < NEXP; e++)
                acc[t][e] += __shfl_xor_sync(0xffffffffu, acc[t][e], off);
    }

    // Lanes 0..TOKN-1: one token each — top-2 + renorm + writes
    if (lane < TOKN) {
        float l[NEXP];
        #pragma unroll
        for (int t = 0; t < TOKN; t++) {
            if (lane == t) {
                #pragma unroll
                for (int e = 0; e < NEXP; e++) l[e] = acc[t][e];
            }
        }

        const size_t tok = t0 + lane;

        // argmax (ties -> lowest index, matching jax.lax.top_k)
        int   i1 = 0; float v1 = l[0];
        #pragma unroll
        for (int e = 1; e < NEXP; e++)
            if (l[e] > v1) { v1 = l[e]; i1 = e; }
        int   i2 = -1; float v2 = -INFINITY;
        #pragma unroll
        for (int e = 0; e < NEXP; e++)
            if (e != i1 && l[e] > v2) { v2 = l[e]; i2 = e; }

        // renormalized top-2 softmax weights
        const float e2 = __expf(v2 - v1);
        const float r  = 1.0f / (1.0f + e2);

        out_w[tok * 2 + 0] = r;
        out_w[tok * 2 + 1] = e2 * r;
        out_i[tok * 2 + 0] = (float)i1;
        out_i[tok * 2 + 1] = (float)i2;
        #pragma unroll
        for (int e = 0; e < NEXP; e++)
            out_l[tok * NEXP + e] = l[e];
    }
}

__global__ __launch_bounds__(THREADS, 1)
void moe_router_kernel(const float* __restrict__ hs,
                       const float* __restrict__ rw,
                       float* __restrict__ out)
{
    extern __shared__ float sw[];          // [NEXP][HDIM] = 128 KB
    float4* sw4 = reinterpret_cast<float4*>(sw);

    // Stage router weights into shared memory (coalesced, once per block)
    {
        const float4* rw4 = reinterpret_cast<const float4*>(rw);
        for (int i = threadIdx.x; i < NEXP * H4; i += THREADS)
            sw4[i] = rw4[i];
    }
    __syncthreads();

    const int lane = threadIdx.x & 31;
    const int wid  = threadIdx.x >> 5;
    // Interleaved mapping: spreads the 5-token warps across all SMs
    const int gwarp = wid * gridDim.x + blockIdx.x;

    float* out_w = out;                     // [NTOK, 2] top-k weights
    float* out_i = out + (size_t)NTOK * 2;  // [NTOK, 2] indices (as float)
    float* out_l = out + (size_t)NTOK * 4;  // [NTOK, 8] raw logits

    const float4* hsb = reinterpret_cast<const float4*>(hs);

    // One group per warp: warps [0, RBIG) own 5 tokens, the rest own 4.
    if (gwarp < RBIG) {
        const size_t base = (size_t)gwarp * TOK_BIG;
        process_group<TOK_BIG>(base, lane, hsb, sw4, out_w, out_i, out_l);
    } else {
        const size_t base = (size_t)RBIG * TOK_BIG
                          + (size_t)(gwarp - RBIG) * TOK_SMALL;
        process_group<TOK_SMALL>(base, lane, hsb, sw4, out_w, out_i, out_l);
    }
}

extern "C" void kernel_launch(void* const* d_in, const int* in_sizes, int n_in,
                              void* d_out, int out_size)
{
    const float* hs = (const float*)d_in[0];   // hidden_states [4,4096,4096] f32
    const float* rw = (const float*)d_in[1];   // router_weight [8,4096] f32
    float* out = (float*)d_out;

    (void)in_sizes; (void)n_in; (void)out_size;

    cudaFuncSetAttribute(moe_router_kernel,
                         cudaFuncAttributeMaxDynamicSharedMemorySize,
                         NEXP * HDIM * (int)sizeof(float));

    moe_router_kernel<<<BLOCKS, THREADS, NEXP * HDIM * sizeof(float)>>>(hs, rw, out);
}